// round 2
// baseline (speedup 1.0000x reference)
#include <cuda_runtime.h>
#include <math.h>

#define NN 20000
#define NE 40000
#define NG 1000

typedef unsigned long long ull;

// Scratch (static __device__ — no allocations allowed)
__device__ float d_h[(size_t)NE * 128];          // edge MLP hidden
__device__ float d_w2t[64 * 8192];               // transposed w2: [mi][128*mo]
__device__ float d_P[(size_t)NN * 8192];         // per-node precomputed P
__device__ float d_Q[NN * 64];                   // b2 contribution per node
__device__ float d_xa[NN * 64];
__device__ float d_xb[NN * 64];
__device__ float d_agg[NN * 64];
__device__ float d_sums[NG * 64];
__device__ float d_cnt[NG];

__device__ __forceinline__ float eluf(float v) { return v > 0.f ? v : expm1f(v); }

__device__ __forceinline__ ull pk2(float lo, float hi) {
    ull r; asm("mov.b64 %0, {%1, %2};" : "=l"(r) : "f"(lo), "f"(hi)); return r;
}
__device__ __forceinline__ void fma2(ull& d, ull a, ull b) {
    asm("fma.rn.f32x2 %0, %1, %2, %0;" : "+l"(d) : "l"(a), "l"(b));
}
__device__ __forceinline__ float2 u2f2(ull v) {
    float2 f; asm("mov.b64 {%0, %1}, %2;" : "=f"(f.x), "=f"(f.y) : "l"(v)); return f;
}

__global__ void zerok(float* __restrict__ p, int n) {
    int i = blockIdx.x * blockDim.x + threadIdx.x;
    if (i < n) p[i] = 0.f;
}

// h[e,j] = relu(b1[j] + sum_a ea[e,a]*w1[a,j]),  j in [0,128)
__global__ void edge_mlp_k(const float* __restrict__ ea, const float* __restrict__ w1,
                           const float* __restrict__ b1, float* __restrict__ h) {
    int e = blockIdx.x, j = threadIdx.x;
    __shared__ float a[5];
    if (j < 5) a[j] = ea[e * 5 + j];
    __syncthreads();
    float s = b1[j];
#pragma unroll
    for (int t = 0; t < 5; t++) s = fmaf(a[t], w1[t * 128 + j], s);
    h[(size_t)e * 128 + j] = fmaxf(s, 0.f);
}

// w2t[i, k*mo+o] = w2[k, i*mo+o]
__global__ void transpose_w2_k(const float* __restrict__ w2, float* __restrict__ w2t,
                               int mi, int mo, int NC, int tot) {
    int idx = blockIdx.x * blockDim.x + threadIdx.x;
    if (idx >= tot) return;
    int k = idx / (mi * mo);
    int r = idx - k * mi * mo;
    int i = r / mo;
    int o = r - i * mo;
    w2t[i * NC + k * mo + o] = w2[idx];
}

// P[n, c] = sum_i X[n,i] * Wt[i, c]  — 64x128 tile, 256 thr, f32x2 packed FMA.
// Each thread: 4 rows x 8 cols (4 f32x2 pairs).
template<int K>
__global__ void gemmP2_k(const float* __restrict__ X,
                         const float* __restrict__ Wt, int NC,
                         float* __restrict__ P) {
    __shared__ float Xs[64][K];     // [row][i] — coalesced fill, broadcast reads
    __shared__ float Ws[K][128];    // [i][col] — f32x2-packed reads
    int c0 = blockIdx.x * 128, n0 = blockIdx.y * 64;
    int tid = threadIdx.x;
    int tx = tid & 15, ty = tid >> 4;

    for (int idx = tid; idx < 64 * K; idx += 256) {
        int r = idx / K, i = idx - r * K;     // consecutive tid -> consecutive i (coalesced gmem)
        int n = n0 + r;
        Xs[r][i] = (n < NN) ? X[n * K + i] : 0.f;
    }
    for (int idx = tid; idx < K * 128; idx += 256) {
        int i = idx >> 7, c = idx & 127;
        Ws[i][c] = Wt[i * NC + c0 + c];
    }
    __syncthreads();

    ull acc[4][4] = {};
#pragma unroll 4
    for (int k = 0; k < K; k++) {
        ulonglong2 b01 = *(const ulonglong2*)&Ws[k][tx * 8];
        ulonglong2 b23 = *(const ulonglong2*)&Ws[k][tx * 8 + 4];
#pragma unroll
        for (int r = 0; r < 4; r++) {
            float a = Xs[ty * 4 + r][k];
            ull aa = pk2(a, a);
            fma2(acc[r][0], aa, b01.x);
            fma2(acc[r][1], aa, b01.y);
            fma2(acc[r][2], aa, b23.x);
            fma2(acc[r][3], aa, b23.y);
        }
    }
#pragma unroll
    for (int r = 0; r < 4; r++) {
        int n = n0 + ty * 4 + r;
        if (n < NN) {
            ulonglong2 v0 = make_ulonglong2(acc[r][0], acc[r][1]);
            ulonglong2 v1 = make_ulonglong2(acc[r][2], acc[r][3]);
            *(ulonglong2*)&P[(size_t)n * NC + c0 + tx * 8] = v0;
            *(ulonglong2*)&P[(size_t)n * NC + c0 + tx * 8 + 4] = v1;
        }
    }
}

// Q[n,o] = sum_i X[n,i] * b2[i*mo+o]   (b2 term of the edge-MLP output)
__global__ void qk(const float* __restrict__ X, const float* __restrict__ b2,
                   float* __restrict__ Q, int mi, int mo, int tot) {
    int idx = blockIdx.x * blockDim.x + threadIdx.x;
    if (idx >= tot) return;
    int n = idx / mo, o = idx - n * mo;
    float s = 0.f;
    for (int i = 0; i < mi; i++) s = fmaf(X[n * mi + i], b2[i * mo + o], s);
    Q[idx] = s;
}

// msg[e,o2] = Q[src,o2] + sum_k h[e,k] * P[src, k*MO + o2];  atomic agg[dst] +=
// f32x2: each thread owns 2 outputs; dual accumulators for ILP.
template<int MO>
__global__ void edge_msg2_k(const float* __restrict__ h, const float* __restrict__ P,
                            const float* __restrict__ Q,
                            const int* __restrict__ src, const int* __restrict__ dst,
                            float* __restrict__ agg) {
    constexpr int PO = MO / 2;        // f32x2 lanes per edge
    constexpr int EPB = 128 / PO;     // edges per block
    __shared__ float hs[EPB * 128];
    int le = threadIdx.x / PO, o = threadIdx.x - le * PO;
    int e = blockIdx.x * EPB + le;
    for (int t = threadIdx.x; t < EPB * 128; t += 128)
        hs[t] = h[(size_t)blockIdx.x * (EPB * 128) + t];
    __syncthreads();
    int s = src[e], d = dst[e];
    const float* p = P + (size_t)s * (128 * MO) + o * 2;
    const float* hh = hs + le * 128;
    ull acc0 = *(const ull*)&Q[s * MO + o * 2];
    ull acc1 = 0;                      // packed (0.0f, 0.0f)
#pragma unroll 8
    for (int k = 0; k < 128; k += 2) {
        ull hk0 = pk2(hh[k], hh[k]);
        ull hk1 = pk2(hh[k + 1], hh[k + 1]);
        fma2(acc0, hk0, *(const ull*)&p[(size_t)k * MO]);
        fma2(acc1, hk1, *(const ull*)&p[(size_t)(k + 1) * MO]);
    }
    float2 a0 = u2f2(acc0), a1 = u2f2(acc1);
    atomicAdd(&agg[d * MO + o * 2],     a0.x + a1.x);
    atomicAdd(&agg[d * MO + o * 2 + 1], a0.y + a1.y);
}

// Xout[n,o] = elu( sum_i Xin[n,i]*root[i,o] + agg[n,o] + bias[o] )
__global__ void node_update_k(const float* __restrict__ Xin, const float* __restrict__ root,
                              const float* __restrict__ agg, const float* __restrict__ bias,
                              float* __restrict__ Xout, int mi, int mo, int tot) {
    int idx = blockIdx.x * blockDim.x + threadIdx.x;
    if (idx >= tot) return;
    int n = idx / mo, o = idx - n * mo;
    float s = agg[idx] + bias[o];
    for (int i = 0; i < mi; i++) s = fmaf(Xin[n * mi + i], root[i * mo + o], s);
    Xout[idx] = eluf(s);
}

__global__ void pool_k(const float* __restrict__ X, const int* __restrict__ batch,
                       float* __restrict__ sums, float* __restrict__ cnt) {
    int idx = blockIdx.x * blockDim.x + threadIdx.x;
    if (idx >= NN * 64) return;
    int n = idx >> 6, o = idx & 63;
    int g = batch[n];
    atomicAdd(&sums[g * 64 + o], X[idx]);
    if (o == 0) atomicAdd(&cnt[g], 1.f);
}

__global__ void fc_k(const float* __restrict__ sums, const float* __restrict__ cnt,
                     const float* __restrict__ w1, const float* __restrict__ bb1,
                     const float* __restrict__ w2, const float* __restrict__ bb2,
                     const float* __restrict__ w3, const float* __restrict__ bb3,
                     float* __restrict__ out) {
    int g = blockIdx.x, t = threadIdx.x;
    __shared__ float v[64], t1[32], t2[16];
    float c = fmaxf(cnt[g], 1.f);
    v[t] = sums[g * 64 + t] / c;
    __syncthreads();
    if (t < 32) {
        float s = bb1[t];
        for (int i = 0; i < 64; i++) s = fmaf(v[i], w1[i * 32 + t], s);
        t1[t] = eluf(s);
    }
    __syncthreads();
    if (t < 16) {
        float s = bb2[t];
        for (int i = 0; i < 32; i++) s = fmaf(t1[i], w2[i * 16 + t], s);
        t2[t] = eluf(s);
    }
    __syncthreads();
    if (t == 0) {
        float s = bb3[0];
        for (int i = 0; i < 16; i++) s = fmaf(t2[i], w3[i], s);
        out[g] = s;
    }
}

extern "C" void kernel_launch(void* const* d_in, const int* in_sizes, int n_in,
                              void* d_out, int out_size) {
    const float* x     = (const float*)d_in[0];
    const int*   ei    = (const int*)d_in[1];
    const float* ea    = (const float*)d_in[2];
    const int*   batch = (const int*)d_in[3];
    const float *W1[3], *B1[3], *W2[3], *B2[3], *ROOT[3], *BIAS[3];
    for (int l = 0; l < 3; l++) {
        int b = 4 + 6 * l;
        W1[l]   = (const float*)d_in[b + 0];
        B1[l]   = (const float*)d_in[b + 1];
        W2[l]   = (const float*)d_in[b + 2];
        B2[l]   = (const float*)d_in[b + 3];
        ROOT[l] = (const float*)d_in[b + 4];
        BIAS[l] = (const float*)d_in[b + 5];
    }
    const float* fc1w = (const float*)d_in[22];
    const float* fc1b = (const float*)d_in[23];
    const float* fc2w = (const float*)d_in[24];
    const float* fc2b = (const float*)d_in[25];
    const float* fc3w = (const float*)d_in[26];
    const float* fc3b = (const float*)d_in[27];
    float* out = (float*)d_out;

    float *h, *w2t, *P, *Q, *xa, *xb, *agg, *sums, *cnt;
    cudaGetSymbolAddress((void**)&h, d_h);
    cudaGetSymbolAddress((void**)&w2t, d_w2t);
    cudaGetSymbolAddress((void**)&P, d_P);
    cudaGetSymbolAddress((void**)&Q, d_Q);
    cudaGetSymbolAddress((void**)&xa, d_xa);
    cudaGetSymbolAddress((void**)&xb, d_xb);
    cudaGetSymbolAddress((void**)&agg, d_agg);
    cudaGetSymbolAddress((void**)&sums, d_sums);
    cudaGetSymbolAddress((void**)&cnt, d_cnt);

    const int* src = ei;
    const int* dst = ei + NE;
    const int MI[3] = {13, 32, 64};
    const int MO[3] = {32, 64, 64};
    const float* xin = x;
    float* xouts[3] = {xa, xb, xa};

    for (int l = 0; l < 3; l++) {
        int mi = MI[l], mo = MO[l], NC = 128 * mo;
        edge_mlp_k<<<NE, 128>>>(ea, W1[l], B1[l], h);
        int tot = 128 * mi * mo;
        transpose_w2_k<<<(tot + 255) / 256, 256>>>(W2[l], w2t, mi, mo, NC, tot);
        dim3 gp(NC / 128, (NN + 63) / 64);
        if (l == 0)      gemmP2_k<13><<<gp, 256>>>(xin, w2t, NC, P);
        else if (l == 1) gemmP2_k<32><<<gp, 256>>>(xin, w2t, NC, P);
        else             gemmP2_k<64><<<gp, 256>>>(xin, w2t, NC, P);
        int tq = NN * mo;
        qk<<<(tq + 255) / 256, 256>>>(xin, B2[l], Q, mi, mo, tq);
        zerok<<<(tq + 255) / 256, 256>>>(agg, tq);
        if (l == 0) edge_msg2_k<32><<<NE / 8, 128>>>(h, P, Q, src, dst, agg);
        else        edge_msg2_k<64><<<NE / 4, 128>>>(h, P, Q, src, dst, agg);
        node_update_k<<<(tq + 255) / 256, 256>>>(xin, ROOT[l], agg, BIAS[l], xouts[l], mi, mo, tq);
        xin = xouts[l];
    }
    zerok<<<(NG * 64 + 255) / 256, 256>>>(sums, NG * 64);
    zerok<<<(NG + 255) / 256, 256>>>(cnt, NG);
    pool_k<<<(NN * 64 + 255) / 256, 256>>>(xin, batch, sums, cnt);
    fc_k<<<NG, 64>>>(sums, cnt, fc1w, fc1b, fc2w, fc2b, fc3w, fc3b, out);
}

// round 4
// speedup vs baseline: 1.1286x; 1.1286x over previous
#include <cuda_runtime.h>
#include <math.h>

#define NN 20000
#define NE 40000
#define NG 1000

// ---------------- scratch (static __device__ — no allocations) ----------------
__device__ float d_h[(size_t)NE * 128];          // edge MLP hidden
__device__ float d_w2t[64 * 8192];               // transposed w2: [i][k*mo+o]
__device__ float d_P[(size_t)NN * 8192];         // per-node precomputed P
__device__ float d_Q[NN * 64];                   // b2 contribution per node
__device__ float d_xa[NN * 64];
__device__ float d_xb[NN * 64];
__device__ float d_agg[NN * 64];
__device__ float d_sums[NG * 64];
__device__ float d_cnt[NG];
// CSR (edges sorted by src) — built once per launch
__device__ int d_ecnt[NN];
__device__ int d_etmp[NN];
__device__ int d_rowp[NN + 1];
__device__ int d_csrc[NE];
__device__ int d_cdst[NE];
__device__ int d_ceid[NE];

__device__ __forceinline__ float eluf(float v) { return v > 0.f ? v : expm1f(v); }

__global__ void zerok(float* __restrict__ p, int n) {
    int i = blockIdx.x * blockDim.x + threadIdx.x;
    if (i < n) p[i] = 0.f;
}
__global__ void zeroik(int* __restrict__ p, int n) {
    int i = blockIdx.x * blockDim.x + threadIdx.x;
    if (i < n) p[i] = 0;
}

// ---------------- CSR build ----------------
__global__ void hist_k(const int* __restrict__ src, int* __restrict__ cnt) {
    int e = blockIdx.x * blockDim.x + threadIdx.x;
    if (e < NE) atomicAdd(&cnt[src[e]], 1);
}
// single-block exclusive scan of cnt[NN] -> rowp[NN+1]
__global__ void scan_k(const int* __restrict__ cnt, int* __restrict__ rowp) {
    __shared__ int sh[1024];
    __shared__ int carry;
    if (threadIdx.x == 0) carry = 0;
    __syncthreads();
    for (int base = 0; base < NN; base += 1024) {
        int i = base + threadIdx.x;
        int v = (i < NN) ? cnt[i] : 0;
        sh[threadIdx.x] = v;
        __syncthreads();
        for (int off = 1; off < 1024; off <<= 1) {
            int t = (threadIdx.x >= off) ? sh[threadIdx.x - off] : 0;
            __syncthreads();
            sh[threadIdx.x] += t;
            __syncthreads();
        }
        if (i < NN) rowp[i] = carry + sh[threadIdx.x] - v;
        __syncthreads();
        if (threadIdx.x == 1023) carry += sh[1023];
        __syncthreads();
    }
    if (threadIdx.x == 0) rowp[NN] = carry;
}
__global__ void scatter_k(const int* __restrict__ src, const int* __restrict__ dst,
                          const int* __restrict__ rowp, int* __restrict__ tmp,
                          int* __restrict__ csrc, int* __restrict__ cdst,
                          int* __restrict__ ceid) {
    int e = blockIdx.x * blockDim.x + threadIdx.x;
    if (e >= NE) return;
    int s = src[e];
    int pos = rowp[s] + atomicAdd(&tmp[s], 1);
    csrc[pos] = s;
    cdst[pos] = dst[e];
    ceid[pos] = e;
}

// ---------------- edge MLP ----------------
__global__ void edge_mlp_k(const float* __restrict__ ea, const float* __restrict__ w1,
                           const float* __restrict__ b1, float* __restrict__ h) {
    int e = blockIdx.x, j = threadIdx.x;
    __shared__ float a[5];
    if (j < 5) a[j] = ea[e * 5 + j];
    __syncthreads();
    float s = b1[j];
#pragma unroll
    for (int t = 0; t < 5; t++) s = fmaf(a[t], w1[t * 128 + j], s);
    h[(size_t)e * 128 + j] = fmaxf(s, 0.f);
}

// w2t[i, k*mo+o] = w2[k, i*mo+o]
__global__ void transpose_w2_k(const float* __restrict__ w2, float* __restrict__ w2t,
                               int mi, int mo, int NC, int tot) {
    int idx = blockIdx.x * blockDim.x + threadIdx.x;
    if (idx >= tot) return;
    int k = idx / (mi * mo);
    int r = idx - k * mi * mo;
    int i = r / mo;
    int o = r - i * mo;
    w2t[i * NC + k * mo + o] = w2[idx];
}

// ---------------- GEMM: P[n,c] = sum_i X[n,i]*Wt[i,c] ----------------
// 128x128 tile, 256 threads, 8x8 accumulators per thread, dynamic smem.
template<int K>
__global__ void __launch_bounds__(256) gemmP_k(const float* __restrict__ X,
                                               const float* __restrict__ Wt, int NC,
                                               float* __restrict__ P) {
    extern __shared__ float smf[];
    float* Xs = smf;                       // [128][K+1]
    float* Ws = smf + 128 * (K + 1);       // [K][128]
    int c0 = blockIdx.x * 128, n0 = blockIdx.y * 128;
    int tid = threadIdx.x, tx = tid & 15, ty = tid >> 4;

    for (int idx = tid; idx < 128 * K; idx += 256) {
        int r = idx / K, i = idx - r * K;          // coalesced gmem
        int n = n0 + r;
        Xs[r * (K + 1) + i] = (n < NN) ? X[n * K + i] : 0.f;
    }
    for (int idx = tid; idx < K * 128; idx += 256) {
        int i = idx >> 7, c = idx & 127;
        Ws[i * 128 + c] = Wt[i * NC + c0 + c];
    }
    __syncthreads();

    float acc[8][8] = {};
#pragma unroll 4
    for (int k = 0; k < K; k++) {
        float4 b0 = *(const float4*)(Ws + k * 128 + tx * 8);
        float4 b1 = *(const float4*)(Ws + k * 128 + tx * 8 + 4);
        float a[8];
#pragma unroll
        for (int rr = 0; rr < 8; rr++) a[rr] = Xs[(ty * 8 + rr) * (K + 1) + k];
#pragma unroll
        for (int rr = 0; rr < 8; rr++) {
            acc[rr][0] = fmaf(a[rr], b0.x, acc[rr][0]);
            acc[rr][1] = fmaf(a[rr], b0.y, acc[rr][1]);
            acc[rr][2] = fmaf(a[rr], b0.z, acc[rr][2]);
            acc[rr][3] = fmaf(a[rr], b0.w, acc[rr][3]);
            acc[rr][4] = fmaf(a[rr], b1.x, acc[rr][4]);
            acc[rr][5] = fmaf(a[rr], b1.y, acc[rr][5]);
            acc[rr][6] = fmaf(a[rr], b1.z, acc[rr][6]);
            acc[rr][7] = fmaf(a[rr], b1.w, acc[rr][7]);
        }
    }
#pragma unroll
    for (int rr = 0; rr < 8; rr++) {
        int n = n0 + ty * 8 + rr;
        if (n < NN) {
            float* dst = P + (size_t)n * NC + c0 + tx * 8;
            *(float4*)dst       = make_float4(acc[rr][0], acc[rr][1], acc[rr][2], acc[rr][3]);
            *(float4*)(dst + 4) = make_float4(acc[rr][4], acc[rr][5], acc[rr][6], acc[rr][7]);
        }
    }
}

// Q[n,o] = sum_i X[n,i] * b2[i*mo+o]
__global__ void qk(const float* __restrict__ X, const float* __restrict__ b2,
                   float* __restrict__ Q, int mi, int mo, int tot) {
    int idx = blockIdx.x * blockDim.x + threadIdx.x;
    if (idx >= tot) return;
    int n = idx / mo, o = idx - n * mo;
    float s = 0.f;
    for (int i = 0; i < mi; i++) s = fmaf(X[n * mi + i], b2[i * mo + o], s);
    Q[idx] = s;
}

// CSR-ordered edge message: positions p are src-sorted -> P rows reused in L1/L2.
__global__ void edge_msg_k(const float* __restrict__ h, const float* __restrict__ P,
                           const float* __restrict__ Q,
                           const int* __restrict__ csrc, const int* __restrict__ cdst,
                           const int* __restrict__ ceid,
                           float* __restrict__ agg, int NC, int mo) {
    __shared__ float hs[512];
    int epb = 128 / mo;
    int le = threadIdx.x / mo, o = threadIdx.x - le * mo;
    int p = blockIdx.x * epb + le;
    int eid = ceid[p];
    for (int t = o; t < 128; t += mo) hs[le * 128 + t] = h[(size_t)eid * 128 + t];
    __syncthreads();
    int s = csrc[p], d = cdst[p];
    const float* pp = P + (size_t)s * NC + o;
    const float* hh = hs + le * 128;
    float acc = Q[s * mo + o];
#pragma unroll 16
    for (int k = 0; k < 128; k++) acc = fmaf(hh[k], pp[(size_t)k * mo], acc);
    atomicAdd(&agg[d * mo + o], acc);
}

__global__ void node_update_k(const float* __restrict__ Xin, const float* __restrict__ root,
                              const float* __restrict__ agg, const float* __restrict__ bias,
                              float* __restrict__ Xout, int mi, int mo, int tot) {
    int idx = blockIdx.x * blockDim.x + threadIdx.x;
    if (idx >= tot) return;
    int n = idx / mo, o = idx - n * mo;
    float s = agg[idx] + bias[o];
    for (int i = 0; i < mi; i++) s = fmaf(Xin[n * mi + i], root[i * mo + o], s);
    Xout[idx] = eluf(s);
}

__global__ void pool_k(const float* __restrict__ X, const int* __restrict__ batch,
                       float* __restrict__ sums, float* __restrict__ cnt) {
    int idx = blockIdx.x * blockDim.x + threadIdx.x;
    if (idx >= NN * 64) return;
    int n = idx >> 6, o = idx & 63;
    int g = batch[n];
    atomicAdd(&sums[g * 64 + o], X[idx]);
    if (o == 0) atomicAdd(&cnt[g], 1.f);
}

__global__ void fc_k(const float* __restrict__ sums, const float* __restrict__ cnt,
                     const float* __restrict__ w1, const float* __restrict__ bb1,
                     const float* __restrict__ w2, const float* __restrict__ bb2,
                     const float* __restrict__ w3, const float* __restrict__ bb3,
                     float* __restrict__ out) {
    int g = blockIdx.x, t = threadIdx.x;
    __shared__ float v[64], t1[32], t2[16];
    float c = fmaxf(cnt[g], 1.f);
    v[t] = sums[g * 64 + t] / c;
    __syncthreads();
    if (t < 32) {
        float s = bb1[t];
        for (int i = 0; i < 64; i++) s = fmaf(v[i], w1[i * 32 + t], s);
        t1[t] = eluf(s);
    }
    __syncthreads();
    if (t < 16) {
        float s = bb2[t];
        for (int i = 0; i < 32; i++) s = fmaf(t1[i], w2[i * 16 + t], s);
        t2[t] = eluf(s);
    }
    __syncthreads();
    if (t == 0) {
        float s = bb3[0];
        for (int i = 0; i < 16; i++) s = fmaf(t2[i], w3[i], s);
        out[g] = s;
    }
}

// ---------------- launch ----------------
extern "C" void kernel_launch(void* const* d_in, const int* in_sizes, int n_in,
                              void* d_out, int out_size) {
    const float* x     = (const float*)d_in[0];
    const int*   ei    = (const int*)d_in[1];
    const float* ea    = (const float*)d_in[2];
    const int*   batch = (const int*)d_in[3];
    const float *W1[3], *B1[3], *W2[3], *B2[3], *ROOT[3], *BIAS[3];
    for (int l = 0; l < 3; l++) {
        int b = 4 + 6 * l;
        W1[l]   = (const float*)d_in[b + 0];
        B1[l]   = (const float*)d_in[b + 1];
        W2[l]   = (const float*)d_in[b + 2];
        B2[l]   = (const float*)d_in[b + 3];
        ROOT[l] = (const float*)d_in[b + 4];
        BIAS[l] = (const float*)d_in[b + 5];
    }
    const float* fc1w = (const float*)d_in[22];
    const float* fc1b = (const float*)d_in[23];
    const float* fc2w = (const float*)d_in[24];
    const float* fc2b = (const float*)d_in[25];
    const float* fc3w = (const float*)d_in[26];
    const float* fc3b = (const float*)d_in[27];
    float* out = (float*)d_out;

    float *h, *w2t, *P, *Q, *xa, *xb, *agg, *sums, *cnt;
    int *ecnt, *etmp, *rowp, *csrc, *cdst, *ceid;
    cudaGetSymbolAddress((void**)&h, d_h);
    cudaGetSymbolAddress((void**)&w2t, d_w2t);
    cudaGetSymbolAddress((void**)&P, d_P);
    cudaGetSymbolAddress((void**)&Q, d_Q);
    cudaGetSymbolAddress((void**)&xa, d_xa);
    cudaGetSymbolAddress((void**)&xb, d_xb);
    cudaGetSymbolAddress((void**)&agg, d_agg);
    cudaGetSymbolAddress((void**)&sums, d_sums);
    cudaGetSymbolAddress((void**)&cnt, d_cnt);
    cudaGetSymbolAddress((void**)&ecnt, d_ecnt);
    cudaGetSymbolAddress((void**)&etmp, d_etmp);
    cudaGetSymbolAddress((void**)&rowp, d_rowp);
    cudaGetSymbolAddress((void**)&csrc, d_csrc);
    cudaGetSymbolAddress((void**)&cdst, d_cdst);
    cudaGetSymbolAddress((void**)&ceid, d_ceid);

    const int* src = ei;
    const int* dst = ei + NE;

    // CSR build (deterministic inputs; order within a src bin may vary — only
    // affects float atomic-add order, same as the existing atomics)
    zeroik<<<(NN + 255) / 256, 256>>>(ecnt, NN);
    zeroik<<<(NN + 255) / 256, 256>>>(etmp, NN);
    hist_k<<<(NE + 255) / 256, 256>>>(src, ecnt);
    scan_k<<<1, 1024>>>(ecnt, rowp);
    scatter_k<<<(NE + 255) / 256, 256>>>(src, dst, rowp, etmp, csrc, cdst, ceid);

    // GEMM smem sizes
    const int SM13 = (128 * 14 + 13 * 128) * 4;
    const int SM32 = (128 * 33 + 32 * 128) * 4;
    const int SM64 = (128 * 65 + 64 * 128) * 4;   // 66048
    cudaFuncSetAttribute(gemmP_k<13>, cudaFuncAttributeMaxDynamicSharedMemorySize, SM13);
    cudaFuncSetAttribute(gemmP_k<32>, cudaFuncAttributeMaxDynamicSharedMemorySize, SM32);
    cudaFuncSetAttribute(gemmP_k<64>, cudaFuncAttributeMaxDynamicSharedMemorySize, SM64);

    const int MI[3] = {13, 32, 64};
    const int MO[3] = {32, 64, 64};
    const float* xin = x;
    float* xouts[3] = {xa, xb, xa};

    for (int l = 0; l < 3; l++) {
        int mi = MI[l], mo = MO[l], NC = 128 * mo;
        edge_mlp_k<<<NE, 128>>>(ea, W1[l], B1[l], h);
        int tot = 128 * mi * mo;
        transpose_w2_k<<<(tot + 255) / 256, 256>>>(W2[l], w2t, mi, mo, NC, tot);
        dim3 gp(NC / 128, (NN + 127) / 128);
        if (l == 0)      gemmP_k<13><<<gp, 256, SM13>>>(xin, w2t, NC, P);
        else if (l == 1) gemmP_k<32><<<gp, 256, SM32>>>(xin, w2t, NC, P);
        else             gemmP_k<64><<<gp, 256, SM64>>>(xin, w2t, NC, P);
        int tq = NN * mo;
        qk<<<(tq + 255) / 256, 256>>>(xin, B2[l], Q, mi, mo, tq);
        zerok<<<(tq + 255) / 256, 256>>>(agg, tq);
        edge_msg_k<<<NE * mo / 128, 128>>>(h, P, Q, csrc, cdst, ceid, agg, NC, mo);
        node_update_k<<<(tq + 255) / 256, 256>>>(xin, ROOT[l], agg, BIAS[l], xouts[l], mi, mo, tq);
        xin = xouts[l];
    }
    zerok<<<(NG * 64 + 255) / 256, 256>>>(sums, NG * 64);
    zerok<<<(NG + 255) / 256, 256>>>(cnt, NG);
    pool_k<<<(NN * 64 + 255) / 256, 256>>>(xin, batch, sums, cnt);
    fc_k<<<NG, 64>>>(sums, cnt, fc1w, fc1b, fc2w, fc2b, fc3w, fc3b, out);
}